// round 13
// baseline (speedup 1.0000x reference)
#include <cuda_runtime.h>
#include <cuda_bf16.h>

#define NN 375
#define CC 5
#define FF 64
#define DD 13
#define WPB 4
#define INF30 1e30f

__device__ __forceinline__ int seg_start(int s) { return s == 0 ? 0 : 13 * s - 1; }

__device__ __forceinline__ float tok_load(unsigned q,
                                          const float* __restrict__ t0,
                                          const float* __restrict__ t1,
                                          const float* __restrict__ t2,
                                          const float* __restrict__ t3,
                                          const float* __restrict__ t4) {
    unsigned s = q / 13u;          // unsigned magic-multiply
    unsigned j = q - 13u * s;
    const float* tp = (s == 0) ? t0 : (s == 1) ? t1 : (s == 2) ? t2 : (s == 3) ? t3 : t4;
    return tp[j];
}

// Monotone map fp32 -> u32 (total order matching <, modulo -0/+0)
__device__ __forceinline__ unsigned f2key(float f) {
    unsigned u = __float_as_uint(f);
    return (u & 0x80000000u) ? ~u : (u | 0x80000000u);
}

__global__ void __launch_bounds__(32 * WPB, 1)
token_kernel(const float* __restrict__ pic,
             const float* __restrict__ t0, const float* __restrict__ t1,
             const float* __restrict__ t2, const float* __restrict__ t3,
             const float* __restrict__ t4,
             float* __restrict__ out) {
    __shared__ float sp[WPB][CC * FF];
    __shared__ float Ts[WPB][CC * DD + 3];

    const int warp = threadIdx.x >> 5;
    const int lane = threadIdx.x & 31;
    const int n = blockIdx.x * WPB + warp;
    if (n >= NN) return;   // whole-warp exit; warps fully independent, no block sync

    // ---- Issue ALL global loads up front (overlapped latency) ----
    const float4* p4 = (const float4*)(pic + (size_t)n * (CC * FF));
    float4 r0 = p4[lane];
    float4 r1 = p4[lane + 32];
    float4 r2 = make_float4(0.f, 0.f, 0.f, 0.f);
    if (lane < 16) r2 = p4[lane + 64];

    float tv0 = tok_load(lane, t0, t1, t2, t3, t4);
    float tv1 = tok_load(lane + 32, t0, t1, t2, t3, t4);
    float tv2 = (lane == 0) ? t4[12] : 0.f;

    // ---- Per-lane channel partials (each float4 lies inside one channel) ----
    float s0 = r0.x * r0.x + r0.y * r0.y + r0.z * r0.z + r0.w * r0.w;  // ch0 (lanes<16) / ch1
    float s1 = r1.x * r1.x + r1.y * r1.y + r1.z * r1.z + r1.w * r1.w;  // ch2 / ch3
    float s2 = r2.x * r2.x + r2.y * r2.y + r2.z * r2.z + r2.w * r2.w;  // ch4 (lanes<16 only)

    // 4-stage butterfly within 16-lane halves
    #pragma unroll
    for (int off = 8; off >= 1; off >>= 1) {
        s0 += __shfl_xor_sync(0xffffffffu, s0, off);
        s1 += __shfl_xor_sync(0xffffffffu, s1, off);
        s2 += __shfl_xor_sync(0xffffffffu, s2, off);
    }
    // lanes 0-15: s0=ch0, s1=ch2, s2=ch4 ; lanes 16-31: s0=ch1, s1=ch3

    // ---- Stage row + tokens into shared ----
    float4* sp4 = (float4*)sp[warp];
    sp4[lane]      = r0;
    sp4[lane + 32] = r1;
    if (lane < 16) sp4[lane + 64] = r2;
    Ts[warp][lane]      = tv0;
    Ts[warp][lane + 32] = tv1;
    if (lane == 0) Ts[warp][64] = tv2;

    // Pick up this lane's full_sq[c] (c = lane/5 for lanes < 25)
    int c = lane / 5;
    int s = lane - 5 * c;
    int srcA = ((c & 1) ? 16 : 0);
    float t0s = __shfl_sync(0xffffffffu, s0, srcA);
    float t1s = __shfl_sync(0xffffffffu, s1, srcA);
    float t2s = __shfl_sync(0xffffffffu, s2, 0);
    float fsq = (c < 2) ? t0s : ((c < 4) ? t1s : t2s);

    __syncwarp();

    // ---- Dmat entry per lane (lanes 0..24), formula/order mirrors reference ----
    float Dl = INF30;
    if (lane < 25) {
        const float* row = &sp[warp][c * FF];
        const float* tok = &Ts[warp][s * DD];
        int st = seg_start(s);
        float sa = 0.f, sb = 0.f, da = 0.f, db = 0.f;
        #pragma unroll
        for (int j = 0; j < DD; j += 2) {
            float v = row[st + j];
            float d = v - tok[j];
            sa += v * v;
            da += d * d;
            if (j + 1 < DD) {
                float v2 = row[st + j + 1];
                float d2 = v2 - tok[j + 1];
                sb += v2 * v2;
                db += d2 * d2;
            }
        }
        Dl = fsq - (sa + sb) + (da + db);
    }

    // ---- Greedy matching via REDUX + ballot; 4 rounds + forced last cell.
    //      Tie-break = smallest flat index = exact jnp.argmin semantics.
    //      Assignment packed 3 bits per row: asgp[3r..3r+2] = assigned col. ----
    const unsigned key = f2key(Dl);
    unsigned excl = 0xFE000000u;          // lanes >= 25 permanently excluded
    unsigned asgp = 0u;
    #pragma unroll
    for (int it = 0; it < 4; it++) {
        unsigned k = ((excl >> lane) & 1u) ? 0xFFFFFFFFu : key;
        unsigned mn = __reduce_min_sync(0xffffffffu, k);
        unsigned ball = __ballot_sync(0xffffffffu, k == mn);
        unsigned idx = __ffs(ball) - 1u;
        unsigned r  = idx / 5u;
        unsigned cc = idx - 5u * r;
        excl |= (0x1Fu << (5u * r)) | (0x108421u << cc);
        asgp |= cc << (3u * r);
    }
    {   // exactly one unexcluded cell remains in bits [0,25)
        unsigned idx = __ffs(~excl) - 1u;
        unsigned r  = idx / 5u;
        unsigned cc = idx - 5u * r;
        asgp |= cc << (3u * r);
    }

    // ---- Write output: zeros except out[n,c,start(c)+j] = T[asg[c]][j] ----
    float* orow = out + (size_t)n * (CC * FF);
    #pragma unroll
    for (int k2 = 0; k2 < 3; k2++) {
        if (k2 == 2 && lane >= 16) break;
        int p = lane + 32 * k2;
        int ch = p >> 4;                   // channel = (4p)>>6 = p>>4
        unsigned aa = (asgp >> (3 * ch)) & 7u;
        int base = ((4 * p) & 63) - seg_start(ch);
        const float* tok = &Ts[warp][aa * DD];
        float4 v;
        v.x = (base     >= 0 && base     < DD) ? tok[base]     : 0.f;
        v.y = (base + 1 >= 0 && base + 1 < DD) ? tok[base + 1] : 0.f;
        v.z = (base + 2 >= 0 && base + 2 < DD) ? tok[base + 2] : 0.f;
        v.w = (base + 3 >= 0 && base + 3 < DD) ? tok[base + 3] : 0.f;
        ((float4*)orow)[p] = v;
    }
}

extern "C" void kernel_launch(void* const* d_in, const int* in_sizes, int n_in,
                              void* d_out, int out_size) {
    const float* pic = (const float*)d_in[0];
    const float* t0  = (const float*)d_in[1];
    const float* t1  = (const float*)d_in[2];
    const float* t2  = (const float*)d_in[3];
    const float* t3  = (const float*)d_in[4];
    const float* t4  = (const float*)d_in[5];
    float* out = (float*)d_out;

    const int blocks = (NN + WPB - 1) / WPB;  // 94
    token_kernel<<<blocks, 32 * WPB>>>(pic, t0, t1, t2, t3, t4, out);
}

// round 14
// speedup vs baseline: 1.0657x; 1.0657x over previous
#include <cuda_runtime.h>
#include <cuda_bf16.h>

#define NN 375
#define CC 5
#define FF 64
#define DD 13
#define WPB 4
#define INF30 1e30f

__device__ __forceinline__ int seg_start(int s) { return s == 0 ? 0 : 13 * s - 1; }

__device__ __forceinline__ float tok_load(unsigned q,
                                          const float* __restrict__ t0,
                                          const float* __restrict__ t1,
                                          const float* __restrict__ t2,
                                          const float* __restrict__ t3,
                                          const float* __restrict__ t4) {
    unsigned s = q / 13u;          // unsigned magic-multiply
    unsigned j = q - 13u * s;
    const float* tp = (s == 0) ? t0 : (s == 1) ? t1 : (s == 2) ? t2 : (s == 3) ? t3 : t4;
    return tp[j];
}

// Monotone map fp32 -> u32 (total order matching <, modulo -0/+0)
__device__ __forceinline__ unsigned f2key(float f) {
    unsigned u = __float_as_uint(f);
    return (u & 0x80000000u) ? ~u : (u | 0x80000000u);
}

__global__ void __launch_bounds__(32 * WPB, 1)
token_kernel(const float* __restrict__ pic,
             const float* __restrict__ t0, const float* __restrict__ t1,
             const float* __restrict__ t2, const float* __restrict__ t3,
             const float* __restrict__ t4,
             float* __restrict__ out) {
    __shared__ float sp[WPB][CC * FF];
    __shared__ float Ts[WPB][CC * DD + 3];

    const int warp = threadIdx.x >> 5;
    const int lane = threadIdx.x & 31;
    const int n = blockIdx.x * WPB + warp;
    if (n >= NN) return;   // whole-warp exit; warps fully independent, no block sync

    // ---- Issue ALL global loads up front (overlapped latency) ----
    const float4* p4 = (const float4*)(pic + (size_t)n * (CC * FF));
    float4 r0 = p4[lane];
    float4 r1 = p4[lane + 32];
    float4 r2 = make_float4(0.f, 0.f, 0.f, 0.f);
    if (lane < 16) r2 = p4[lane + 64];

    float tv0 = tok_load(lane, t0, t1, t2, t3, t4);
    float tv1 = tok_load(lane + 32, t0, t1, t2, t3, t4);
    float tv2 = (lane == 0) ? t4[12] : 0.f;

    // ---- Per-lane channel partials (each float4 lies inside one channel) ----
    float s0 = r0.x * r0.x + r0.y * r0.y + r0.z * r0.z + r0.w * r0.w;  // ch0 (lanes<16) / ch1
    float s1 = r1.x * r1.x + r1.y * r1.y + r1.z * r1.z + r1.w * r1.w;  // ch2 / ch3
    float s2 = r2.x * r2.x + r2.y * r2.y + r2.z * r2.z + r2.w * r2.w;  // ch4 (lanes<16 only)

    // 4-stage butterfly within 16-lane halves
    #pragma unroll
    for (int off = 8; off >= 1; off >>= 1) {
        s0 += __shfl_xor_sync(0xffffffffu, s0, off);
        s1 += __shfl_xor_sync(0xffffffffu, s1, off);
        s2 += __shfl_xor_sync(0xffffffffu, s2, off);
    }
    // lanes 0-15: s0=ch0, s1=ch2, s2=ch4 ; lanes 16-31: s0=ch1, s1=ch3

    // ---- Stage row + tokens into shared ----
    float4* sp4 = (float4*)sp[warp];
    sp4[lane]      = r0;
    sp4[lane + 32] = r1;
    if (lane < 16) sp4[lane + 64] = r2;
    Ts[warp][lane]      = tv0;
    Ts[warp][lane + 32] = tv1;
    if (lane == 0) Ts[warp][64] = tv2;

    // Pick up this lane's full_sq[c] (c = lane/5 for lanes < 25)
    int c = lane / 5;
    int s = lane - 5 * c;
    int srcA = ((c & 1) ? 16 : 0);
    float t0s = __shfl_sync(0xffffffffu, s0, srcA);
    float t1s = __shfl_sync(0xffffffffu, s1, srcA);
    float t2s = __shfl_sync(0xffffffffu, s2, 0);
    float fsq = (c < 2) ? t0s : ((c < 4) ? t1s : t2s);

    __syncwarp();

    // ---- Dmat entry per lane (lanes 0..24), formula/order mirrors reference ----
    float Dl = INF30;
    if (lane < 25) {
        const float* row = &sp[warp][c * FF];
        const float* tok = &Ts[warp][s * DD];
        int st = seg_start(s);
        float sa = 0.f, sb = 0.f, da = 0.f, db = 0.f;
        #pragma unroll
        for (int j = 0; j < DD; j += 2) {
            float v = row[st + j];
            float d = v - tok[j];
            sa += v * v;
            da += d * d;
            if (j + 1 < DD) {
                float v2 = row[st + j + 1];
                float d2 = v2 - tok[j + 1];
                sb += v2 * v2;
                db += d2 * d2;
            }
        }
        Dl = fsq - (sa + sb) + (da + db);
    }

    // ---- Greedy matching via REDUX + ballot; 4 rounds + forced last cell.
    //      Tie-break = smallest flat index = exact jnp.argmin semantics.
    //      Assignment packed 3 bits per row: asgp[3r..3r+2] = assigned col. ----
    const unsigned key = f2key(Dl);
    unsigned excl = 0xFE000000u;          // lanes >= 25 permanently excluded
    unsigned asgp = 0u;
    #pragma unroll
    for (int it = 0; it < 4; it++) {
        unsigned k = ((excl >> lane) & 1u) ? 0xFFFFFFFFu : key;
        unsigned mn = __reduce_min_sync(0xffffffffu, k);
        unsigned ball = __ballot_sync(0xffffffffu, k == mn);
        unsigned idx = __ffs(ball) - 1u;
        unsigned r  = idx / 5u;
        unsigned cc = idx - 5u * r;
        excl |= (0x1Fu << (5u * r)) | (0x108421u << cc);
        asgp |= cc << (3u * r);
    }
    {   // exactly one unexcluded cell remains in bits [0,25)
        unsigned idx = __ffs(~excl) - 1u;
        unsigned r  = idx / 5u;
        unsigned cc = idx - 5u * r;
        asgp |= cc << (3u * r);
    }

    // ---- Write output: zeros except out[n,c,start(c)+j] = T[asg[c]][j] ----
    float* orow = out + (size_t)n * (CC * FF);
    #pragma unroll
    for (int k2 = 0; k2 < 3; k2++) {
        if (k2 == 2 && lane >= 16) break;
        int p = lane + 32 * k2;
        int ch = p >> 4;                   // channel = (4p)>>6 = p>>4
        unsigned aa = (asgp >> (3 * ch)) & 7u;
        int base = ((4 * p) & 63) - seg_start(ch);
        const float* tok = &Ts[warp][aa * DD];
        float4 v;
        v.x = (base     >= 0 && base     < DD) ? tok[base]     : 0.f;
        v.y = (base + 1 >= 0 && base + 1 < DD) ? tok[base + 1] : 0.f;
        v.z = (base + 2 >= 0 && base + 2 < DD) ? tok[base + 2] : 0.f;
        v.w = (base + 3 >= 0 && base + 3 < DD) ? tok[base + 3] : 0.f;
        ((float4*)orow)[p] = v;
    }
}

extern "C" void kernel_launch(void* const* d_in, const int* in_sizes, int n_in,
                              void* d_out, int out_size) {
    const float* pic = (const float*)d_in[0];
    const float* t0  = (const float*)d_in[1];
    const float* t1  = (const float*)d_in[2];
    const float* t2  = (const float*)d_in[3];
    const float* t3  = (const float*)d_in[4];
    const float* t4  = (const float*)d_in[5];
    float* out = (float*)d_out;

    const int blocks = (NN + WPB - 1) / WPB;  // 94
    token_kernel<<<blocks, 32 * WPB>>>(pic, t0, t1, t2, t3, t4, out);
}